// round 7
// baseline (speedup 1.0000x reference)
#include <cuda_runtime.h>
#include <cstdint>

#define NS 50000
#define NT 50000
#define NE 800000
#define D  128
#define NTOT (NS + NT)
#define SCAN_BS 1024
#define NBLK ((NT + SCAN_BS - 1) / SCAN_BS)   // 49

// ---------------- scratch (device globals; no allocation allowed) ----------------
__device__ int   g_deg[NT];
__device__ int   g_cursor[NT];
__device__ int   g_rowstart[NT];
__device__ int   g_blocksum[64];
__device__ int   g_blockoff[64];
__device__ int   g_srcidx[NE];
__device__ __align__(16) float g_agg[(size_t)NT * D];

// ---------------- K0: zero counters ----------------
__global__ void k_zero() {
    int i = blockIdx.x * blockDim.x + threadIdx.x;
    if (i < NT) { g_deg[i] = 0; g_cursor[i] = 0; }
}

// ---------------- K1: in-degree histogram (edge_index is int32: JAX x64 off) ----
__global__ void k_count(const int* __restrict__ ei) {
    int e = blockIdx.x * blockDim.x + threadIdx.x;
    if (e < NE) atomicAdd(&g_deg[ei[NE + e]], 1);
}

// ---------------- K2a: per-block exclusive scan ----------------
__global__ __launch_bounds__(SCAN_BS) void k_scanA() {
    __shared__ int sh[SCAN_BS];
    int t = threadIdx.x, b = blockIdx.x;
    int idx = b * SCAN_BS + t;
    int v = (idx < NT) ? g_deg[idx] : 0;
    sh[t] = v;
    __syncthreads();
    for (int off = 1; off < SCAN_BS; off <<= 1) {
        int x = (t >= off) ? sh[t - off] : 0;
        __syncthreads();
        sh[t] += x;
        __syncthreads();
    }
    if (idx < NT) g_rowstart[idx] = sh[t] - v;
    if (t == SCAN_BS - 1) g_blocksum[b] = sh[t];
}

// ---------------- K2b: scan of block sums (64 entries, warp-parallel) --------
__global__ void k_scanB() {
    int t = threadIdx.x;            // 64 threads
    int v = (t < NBLK) ? g_blocksum[t] : 0;
    int x = v;
    #pragma unroll
    for (int off = 1; off < 64; off <<= 1) {
        int y = __shfl_up_sync(0xffffffffu, x, off);
        if ((t & 31) >= off) x += y;
    }
    __shared__ int warp0_total;
    if (t == 31) warp0_total = x;
    __syncthreads();
    int excl = x - v + ((t >= 32) ? warp0_total : 0);
    if (t < NBLK) g_blockoff[t] = excl;
}

// ---------------- K3: fill CSR edge lists ----------------
__global__ void k_fill(const int* __restrict__ ei) {
    int e = blockIdx.x * blockDim.x + threadIdx.x;
    if (e >= NE) return;
    int src = ei[e];
    int dst = ei[NE + e];
    int base = __ldg(&g_rowstart[dst]) + __ldg(&g_blockoff[dst >> 10]);
    int pos  = base + atomicAdd(&g_cursor[dst], 1);
    g_srcidx[pos] = src;
}

// ---------------- K4: gather aggregation (atomic-free) ----------------
// one warp per target row; lane handles one float4 (16 B) of the 512 B row
// a_t[j] = dinv * sum_e x_s[src_e]  +  x_t[j] / (deg+1),  dinv = rsqrt(deg+1)
__global__ __launch_bounds__(256) void k_agg(const float* __restrict__ xs,
                                             const float* __restrict__ xt) {
    int w    = (blockIdx.x * blockDim.x + threadIdx.x) >> 5;
    int lane = threadIdx.x & 31;
    if (w >= NT) return;
    int cnt  = g_deg[w];
    int base = g_rowstart[w] + g_blockoff[w >> 10];

    float4 acc = make_float4(0.f, 0.f, 0.f, 0.f);
    for (int e0 = 0; e0 < cnt; e0 += 16) {
        int s = 0;
        if (lane < 16 && e0 + lane < cnt) s = __ldg(&g_srcidx[base + e0 + lane]);
        int m = min(16, cnt - e0);
        for (int i = 0; i < m; i++) {
            int src = __shfl_sync(0xffffffffu, s, i);
            float4 v = __ldg(reinterpret_cast<const float4*>(xs) + (size_t)src * 32 + lane);
            acc.x += v.x; acc.y += v.y; acc.z += v.z; acc.w += v.w;
        }
    }
    float degp1 = (float)(cnt + 1);
    float dinv  = rsqrtf(degp1);
    float inv   = 1.0f / degp1;
    float4 tv = __ldg(reinterpret_cast<const float4*>(xt) + (size_t)w * 32 + lane);
    acc.x = acc.x * dinv + tv.x * inv;
    acc.y = acc.y * dinv + tv.y * inv;
    acc.z = acc.z * dinv + tv.z * inv;
    acc.w = acc.w * dinv + tv.w * inv;
    reinterpret_cast<float4*>(g_agg)[(size_t)w * 32 + lane] = acc;
}

// ---------------- K5: fused GEMM + ReLU ----------------
// rows 0..NS-1 read x_s, rows NS.. read g_agg (already fully scaled)
#define TILE_M 64
#define KC 32

__global__ __launch_bounds__(256) void k_gemm(const float* __restrict__ xs,
                                              const float* __restrict__ Wm,
                                              float* __restrict__ out) {
    __shared__ float As[TILE_M][KC + 1];
    __shared__ float Ws[KC][D];

    int tid = threadIdx.x;
    int tx  = tid & 15;
    int ty  = tid >> 4;
    int rowBase = blockIdx.x * TILE_M;

    float acc[4][8];
    #pragma unroll
    for (int i = 0; i < 4; i++)
        #pragma unroll
        for (int j = 0; j < 8; j++) acc[i][j] = 0.f;

    for (int kb = 0; kb < D; kb += KC) {
        #pragma unroll
        for (int l = 0; l < 2; l++) {
            int lin = tid + l * 256;
            int r   = lin >> 3;
            int c4  = lin & 7;
            int g   = rowBase + r;
            float4 v = make_float4(0.f, 0.f, 0.f, 0.f);
            if (g < NS) {
                v = reinterpret_cast<const float4*>(xs + (size_t)g * D + kb)[c4];
            } else if (g < NTOT) {
                v = reinterpret_cast<const float4*>(g_agg + (size_t)(g - NS) * D + kb)[c4];
            }
            As[r][c4 * 4 + 0] = v.x;
            As[r][c4 * 4 + 1] = v.y;
            As[r][c4 * 4 + 2] = v.z;
            As[r][c4 * 4 + 3] = v.w;
        }
        #pragma unroll
        for (int l = 0; l < 4; l++) {
            int lin = tid + l * 256;
            int r   = lin >> 5;
            int c4  = lin & 31;
            reinterpret_cast<float4*>(&Ws[r][0])[c4] =
                reinterpret_cast<const float4*>(Wm + (size_t)(kb + r) * D)[c4];
        }
        __syncthreads();

        #pragma unroll
        for (int k = 0; k < KC; k++) {
            float a0 = As[ty * 4 + 0][k];
            float a1 = As[ty * 4 + 1][k];
            float a2 = As[ty * 4 + 2][k];
            float a3 = As[ty * 4 + 3][k];
            float4 b0 = *reinterpret_cast<const float4*>(&Ws[k][tx * 8]);
            float4 b1 = *reinterpret_cast<const float4*>(&Ws[k][tx * 8 + 4]);
            acc[0][0] += a0 * b0.x; acc[0][1] += a0 * b0.y; acc[0][2] += a0 * b0.z; acc[0][3] += a0 * b0.w;
            acc[0][4] += a0 * b1.x; acc[0][5] += a0 * b1.y; acc[0][6] += a0 * b1.z; acc[0][7] += a0 * b1.w;
            acc[1][0] += a1 * b0.x; acc[1][1] += a1 * b0.y; acc[1][2] += a1 * b0.z; acc[1][3] += a1 * b0.w;
            acc[1][4] += a1 * b1.x; acc[1][5] += a1 * b1.y; acc[1][6] += a1 * b1.z; acc[1][7] += a1 * b1.w;
            acc[2][0] += a2 * b0.x; acc[2][1] += a2 * b0.y; acc[2][2] += a2 * b0.z; acc[2][3] += a2 * b0.w;
            acc[2][4] += a2 * b1.x; acc[2][5] += a2 * b1.y; acc[2][6] += a2 * b1.z; acc[2][7] += a2 * b1.w;
            acc[3][0] += a3 * b0.x; acc[3][1] += a3 * b0.y; acc[3][2] += a3 * b0.z; acc[3][3] += a3 * b0.w;
            acc[3][4] += a3 * b1.x; acc[3][5] += a3 * b1.y; acc[3][6] += a3 * b1.z; acc[3][7] += a3 * b1.w;
        }
        __syncthreads();
    }

    #pragma unroll
    for (int i = 0; i < 4; i++) {
        int g = rowBase + ty * 4 + i;
        if (g < NTOT) {
            float4 o0, o1;
            o0.x = fmaxf(acc[i][0], 0.f); o0.y = fmaxf(acc[i][1], 0.f);
            o0.z = fmaxf(acc[i][2], 0.f); o0.w = fmaxf(acc[i][3], 0.f);
            o1.x = fmaxf(acc[i][4], 0.f); o1.y = fmaxf(acc[i][5], 0.f);
            o1.z = fmaxf(acc[i][6], 0.f); o1.w = fmaxf(acc[i][7], 0.f);
            float* po = out + (size_t)g * D + tx * 8;
            *reinterpret_cast<float4*>(po)     = o0;
            *reinterpret_cast<float4*>(po + 4) = o1;
        }
    }
}

// ---------------- launch ----------------
extern "C" void kernel_launch(void* const* d_in, const int* in_sizes, int n_in,
                              void* d_out, int out_size) {
    const int*   ei = (const int*)d_in[0];     // [2, E] int32 (JAX x64 disabled)
    const float* xs = (const float*)d_in[1];   // [NS, 128]
    const float* xt = (const float*)d_in[2];   // [NT, 128]
    const float* W  = (const float*)d_in[3];   // [128, 128]
    float*      out = (float*)d_out;           // [NS+NT, 128]

    k_zero <<<(NT + 255) / 256, 256>>>();
    k_count<<<(NE + 255) / 256, 256>>>(ei);
    k_scanA<<<NBLK, SCAN_BS>>>();
    k_scanB<<<1, 64>>>();
    k_fill <<<(NE + 255) / 256, 256>>>(ei);
    k_agg  <<<(NT * 32 + 255) / 256, 256>>>(xs, xt);
    k_gemm <<<(NTOT + TILE_M - 1) / TILE_M, 256>>>(xs, W, out);
}

// round 8
// speedup vs baseline: 1.2405x; 1.2405x over previous
#include <cuda_runtime.h>
#include <cstdint>

#define NS 50000
#define NT 50000
#define NE 800000
#define D  128
#define NTOT (NS + NT)
#define SCAN_BS 1024
#define NBLK ((NT + SCAN_BS - 1) / SCAN_BS)   // 49

// ---------------- scratch (device globals; no allocation allowed) ----------------
__device__ int   g_deg[NT];
__device__ int   g_cursor[NT];
__device__ int   g_rowstart[NT];
__device__ int   g_blocksum[64];
__device__ int   g_blockoff[64];
__device__ int   g_srcidx[NE];
__device__ __align__(16) float g_agg[(size_t)NT * D];

// packed fp32x2 FMA (Blackwell FFMA2) — exact fp32, 2x throughput
__device__ __forceinline__ void fma2(unsigned long long& d,
                                     unsigned long long a,
                                     unsigned long long b) {
    asm("fma.rn.f32x2 %0, %1, %2, %0;" : "+l"(d) : "l"(a), "l"(b));
}

// ---------------- K0: zero counters ----------------
__global__ void k_zero() {
    int i = blockIdx.x * blockDim.x + threadIdx.x;
    if (i < NT) { g_deg[i] = 0; g_cursor[i] = 0; }
}

// ---------------- K1: in-degree histogram (edge_index is int32) ----------------
__global__ void k_count(const int* __restrict__ ei) {
    int e = blockIdx.x * blockDim.x + threadIdx.x;
    if (e < NE) atomicAdd(&g_deg[ei[NE + e]], 1);
}

// ---------------- K2a: per-block exclusive scan (warp-shuffle) ----------------
__global__ __launch_bounds__(SCAN_BS) void k_scanA() {
    int t = threadIdx.x, b = blockIdx.x;
    int idx = b * SCAN_BS + t;
    int v = (idx < NT) ? g_deg[idx] : 0;
    int lane = t & 31, wid = t >> 5;
    int x = v;
    #pragma unroll
    for (int off = 1; off < 32; off <<= 1) {
        int y = __shfl_up_sync(0xffffffffu, x, off);
        if (lane >= off) x += y;                  // inclusive within warp
    }
    __shared__ int wsum[32];
    if (lane == 31) wsum[wid] = x;
    __syncthreads();
    if (wid == 0) {
        int s = wsum[lane];
        int z = s;
        #pragma unroll
        for (int off = 1; off < 32; off <<= 1) {
            int y = __shfl_up_sync(0xffffffffu, z, off);
            if (lane >= off) z += y;
        }
        wsum[lane] = z - s;                        // exclusive warp offsets
    }
    __syncthreads();
    int incl = x + wsum[wid];
    if (idx < NT) g_rowstart[idx] = incl - v;
    if (t == SCAN_BS - 1) g_blocksum[b] = incl;
}

// ---------------- K2b: scan of block sums (64 entries) ----------------
__global__ void k_scanB() {
    int t = threadIdx.x;            // 64 threads
    int v = (t < NBLK) ? g_blocksum[t] : 0;
    int x = v;
    #pragma unroll
    for (int off = 1; off < 32; off <<= 1) {
        int y = __shfl_up_sync(0xffffffffu, x, off);
        if ((t & 31) >= off) x += y;
    }
    __shared__ int warp0_total;
    if (t == 31) warp0_total = x;
    __syncthreads();
    int excl = x - v + ((t >= 32) ? warp0_total : 0);
    if (t < NBLK) g_blockoff[t] = excl;
}

// ---------------- K3: fill CSR edge lists ----------------
__global__ void k_fill(const int* __restrict__ ei) {
    int e = blockIdx.x * blockDim.x + threadIdx.x;
    if (e >= NE) return;
    int src = ei[e];
    int dst = ei[NE + e];
    int base = __ldg(&g_rowstart[dst]) + __ldg(&g_blockoff[dst >> 10]);
    int pos  = base + atomicAdd(&g_cursor[dst], 1);
    g_srcidx[pos] = src;
}

// ---------------- K4: gather aggregation (atomic-free) ----------------
__global__ __launch_bounds__(256) void k_agg(const float* __restrict__ xs,
                                             const float* __restrict__ xt) {
    int w    = (blockIdx.x * blockDim.x + threadIdx.x) >> 5;
    int lane = threadIdx.x & 31;
    if (w >= NT) return;
    int cnt  = g_deg[w];
    int base = g_rowstart[w] + g_blockoff[w >> 10];

    float4 acc = make_float4(0.f, 0.f, 0.f, 0.f);
    for (int e0 = 0; e0 < cnt; e0 += 16) {
        int s = 0;
        if (lane < 16 && e0 + lane < cnt) s = __ldg(&g_srcidx[base + e0 + lane]);
        int m = min(16, cnt - e0);
        for (int i = 0; i < m; i++) {
            int src = __shfl_sync(0xffffffffu, s, i);
            float4 v = __ldg(reinterpret_cast<const float4*>(xs) + (size_t)src * 32 + lane);
            acc.x += v.x; acc.y += v.y; acc.z += v.z; acc.w += v.w;
        }
    }
    float degp1 = (float)(cnt + 1);
    float dinv  = rsqrtf(degp1);
    float inv   = 1.0f / degp1;
    float4 tv = __ldg(reinterpret_cast<const float4*>(xt) + (size_t)w * 32 + lane);
    acc.x = acc.x * dinv + tv.x * inv;
    acc.y = acc.y * dinv + tv.y * inv;
    acc.z = acc.z * dinv + tv.z * inv;
    acc.w = acc.w * dinv + tv.w * inv;
    reinterpret_cast<float4*>(g_agg)[(size_t)w * 32 + lane] = acc;
}

// ---------------- K5: fused GEMM + ReLU (packed f32x2 FFMA2) ----------------
// 128x128 tile, 256 threads, per-thread 4 rows x 16 cols.
// A stored splatted as float2{a,a}; B as float4[KC][32] with tx-stride-8
// access (conflict-free LDS.128 phases).
#define TILE_M 128
#define KC 32

__global__ __launch_bounds__(256, 2) void k_gemm(const float* __restrict__ xs,
                                                 const float* __restrict__ Wm,
                                                 float* __restrict__ out) {
    __shared__ float2 As2[TILE_M][KC + 1];   // splatted A, padded pitch
    __shared__ float4 Ws4[KC][32];           // B tile: 32 float4 per k-row

    int tid = threadIdx.x;
    int tx  = tid & 7;          // 8 col-groups
    int ty  = tid >> 3;         // 32 row-groups of 4
    int rowBase = blockIdx.x * TILE_M;

    unsigned long long acc[4][8];            // 4 rows x 8 f32x2 pairs (16 cols)
    #pragma unroll
    for (int i = 0; i < 4; i++)
        #pragma unroll
        for (int j = 0; j < 8; j++) acc[i][j] = 0ull;

    for (int kb = 0; kb < D; kb += KC) {
        // ---- load A tile (128 x 32 floats = 1024 float4), splat-store ----
        #pragma unroll
        for (int l = 0; l < 4; l++) {
            int lin = tid + l * 256;          // 0..1023
            int r   = lin >> 3;               // 8 float4 per row
            int c4  = lin & 7;
            int g   = rowBase + r;
            float4 v = make_float4(0.f, 0.f, 0.f, 0.f);
            if (g < NS) {
                v = reinterpret_cast<const float4*>(xs + (size_t)g * D + kb)[c4];
            } else if (g < NTOT) {
                v = reinterpret_cast<const float4*>(g_agg + (size_t)(g - NS) * D + kb)[c4];
            }
            As2[r][c4 * 4 + 0] = make_float2(v.x, v.x);
            As2[r][c4 * 4 + 1] = make_float2(v.y, v.y);
            As2[r][c4 * 4 + 2] = make_float2(v.z, v.z);
            As2[r][c4 * 4 + 3] = make_float2(v.w, v.w);
        }
        // ---- load W tile (32 x 128 floats = 1024 float4) ----
        #pragma unroll
        for (int l = 0; l < 4; l++) {
            int lin = tid + l * 256;
            int r   = lin >> 5;               // 32 float4 per row
            int c4  = lin & 31;
            Ws4[r][c4] = reinterpret_cast<const float4*>(Wm + (size_t)(kb + r) * D)[c4];
        }
        __syncthreads();

        // ---- compute ----
        #pragma unroll
        for (int k = 0; k < KC; k++) {
            unsigned long long a[4];
            #pragma unroll
            for (int i = 0; i < 4; i++) {
                float2 af = As2[ty * 4 + i][k];
                a[i] = *reinterpret_cast<unsigned long long*>(&af);
            }
            #pragma unroll
            for (int j = 0; j < 4; j++) {
                float4 w = Ws4[k][tx + 8 * j];
                unsigned long long b0 = *reinterpret_cast<unsigned long long*>(&w.x);
                unsigned long long b1 = *reinterpret_cast<unsigned long long*>(&w.z);
                #pragma unroll
                for (int i = 0; i < 4; i++) {
                    fma2(acc[i][2 * j + 0], a[i], b0);
                    fma2(acc[i][2 * j + 1], a[i], b1);
                }
            }
        }
        __syncthreads();
    }

    // ---- epilogue: ReLU + store ----
    #pragma unroll
    for (int i = 0; i < 4; i++) {
        int g = rowBase + ty * 4 + i;
        if (g < NTOT) {
            float* po = out + (size_t)g * D;
            #pragma unroll
            for (int j = 0; j < 4; j++) {
                float2 p0 = *reinterpret_cast<float2*>(&acc[i][2 * j + 0]);
                float2 p1 = *reinterpret_cast<float2*>(&acc[i][2 * j + 1]);
                float4 o;
                o.x = fmaxf(p0.x, 0.f); o.y = fmaxf(p0.y, 0.f);
                o.z = fmaxf(p1.x, 0.f); o.w = fmaxf(p1.y, 0.f);
                *reinterpret_cast<float4*>(po + (tx + 8 * j) * 4) = o;
            }
        }
    }
}

// ---------------- launch ----------------
extern "C" void kernel_launch(void* const* d_in, const int* in_sizes, int n_in,
                              void* d_out, int out_size) {
    const int*   ei = (const int*)d_in[0];     // [2, E] int32 (JAX x64 disabled)
    const float* xs = (const float*)d_in[1];   // [NS, 128]
    const float* xt = (const float*)d_in[2];   // [NT, 128]
    const float* W  = (const float*)d_in[3];   // [128, 128]
    float*      out = (float*)d_out;           // [NS+NT, 128]

    k_zero <<<(NT + 255) / 256, 256>>>();
    k_count<<<(NE + 255) / 256, 256>>>(ei);
    k_scanA<<<NBLK, SCAN_BS>>>();
    k_scanB<<<1, 64>>>();
    k_fill <<<(NE + 255) / 256, 256>>>(ei);
    k_agg  <<<(NT * 32 + 255) / 256, 256>>>(xs, xt);
    k_gemm <<<(NTOT + TILE_M - 1) / TILE_M, 256>>>(xs, W, out);
}